// round 3
// baseline (speedup 1.0000x reference)
#include <cuda_runtime.h>
#include <cuda_bf16.h>
#include <cstdint>

// Problem constants
#define BB 8
#define SS 8192
#define DD 1024
#define NROWS (BB * SS)   // 65536 token rows

// Scratch for scores (allocation-free rule: use __device__ global)
__device__ float g_scores[NROWS];

// ---------------------------------------------------------------------------
// Kernel 1: scores[b,s] = dot(hidden[b,s,:], w) + bias
// One warp per token row; float4 vectorized; warp tree reduction.
// ---------------------------------------------------------------------------
__global__ __launch_bounds__(256) void score_kernel(
    const float4* __restrict__ hidden,   // NROWS * 256 float4
    const float4* __restrict__ w4,       // 256 float4
    const float*  __restrict__ bias)
{
    int gwarp = (blockIdx.x * blockDim.x + threadIdx.x) >> 5;
    int lane  = threadIdx.x & 31;
    if (gwarp >= NROWS) return;

    const float4* row = hidden + (size_t)gwarp * (DD / 4);

    float acc = 0.f;
#pragma unroll
    for (int j = 0; j < 8; ++j) {
        float4 x = __ldg(&row[lane + j * 32]);
        float4 w = __ldg(&w4[lane + j * 32]);
        acc = fmaf(x.x, w.x, acc);
        acc = fmaf(x.y, w.y, acc);
        acc = fmaf(x.z, w.z, acc);
        acc = fmaf(x.w, w.w, acc);
    }
#pragma unroll
    for (int o = 16; o > 0; o >>= 1)
        acc += __shfl_down_sync(0xffffffffu, acc, o);

    if (lane == 0)
        g_scores[gwarp] = acc + __ldg(bias);
}

// ---------------------------------------------------------------------------
// Kernel 2: per batch row, exact stable top-k selection via 64-bit radix select
// key = (monotone(score) << 32) | (0xFFFFFFFF - index)  for active tokens
// key = 0                                                for inactive tokens
// Larger key  <=>  earlier in descending stable argsort order. Keys unique.
//
// active_mask is read as 32-bit words with a nonzero test: correct for both
// float32 (1.0f = 0x3F800000) and int32 (1) encodings of the boolean input.
// Output is written as float32 0.0/1.0 (harness promotes bool -> float32).
// ---------------------------------------------------------------------------
__global__ __launch_bounds__(1024) void select_kernel(
    const unsigned int* __restrict__ active,  // [BB, SS] bool as 32-bit words
    float* __restrict__ out)                  // [BB, SS] bool as float32
{
    extern __shared__ unsigned long long keys[];   // SS entries (64 KB)
    __shared__ unsigned int hist[256];
    __shared__ int s_nactive;
    __shared__ unsigned long long s_prefix;
    __shared__ unsigned int s_kk;

    const int row = blockIdx.x;
    const int tid = threadIdx.x;
    const float*        sc = g_scores + (size_t)row * SS;
    const unsigned int* am = active   + (size_t)row * SS;

    if (tid == 0) { s_nactive = 0; s_prefix = 0ull; }
    __syncthreads();

    int local_active = 0;
    for (int i = tid; i < SS; i += 1024) {
        bool a = (am[i] != 0u);
        unsigned int bits = __float_as_uint(sc[i]);
        // monotone transform: larger float -> larger uint
        unsigned int mono = (bits & 0x80000000u) ? ~bits : (bits | 0x80000000u);
        unsigned long long key =
            a ? ((((unsigned long long)mono) << 32) | (unsigned long long)(0xFFFFFFFFu - (unsigned)i))
              : 0ull;
        keys[i] = key;
        local_active += (int)a;
    }
    // warp reduce then shared atomic
#pragma unroll
    for (int o = 16; o > 0; o >>= 1)
        local_active += __shfl_down_sync(0xffffffffu, local_active, o);
    if ((tid & 31) == 0) atomicAdd(&s_nactive, local_active);
    __syncthreads();

    const int n_active = s_nactive;
    // k = max(1, ceil(n_active * 0.5))  (KEEP_RATIO = 0.5, exact integer form)
    unsigned int kk = (unsigned int)max(1, (n_active + 1) >> 1);

    // MSB-first 8-bit radix select of the kk-th largest key
    unsigned long long prefix = 0ull;
    for (int pass = 7; pass >= 0; --pass) {
        const int shift = pass * 8;
        const unsigned long long mask_hi =
            (pass == 7) ? 0ull : ~((1ull << ((pass + 1) * 8)) - 1ull);

        if (tid < 256) hist[tid] = 0u;
        __syncthreads();

        for (int i = tid; i < SS; i += 1024) {
            unsigned long long key = keys[i];
            if ((key & mask_hi) == (prefix & mask_hi)) {
                unsigned int byte = (unsigned int)((key >> shift) & 0xFFull);
                atomicAdd(&hist[byte], 1u);
            }
        }
        __syncthreads();

        if (tid == 0) {
            unsigned int cum = 0;
            int b = 255;
            for (; b >= 0; --b) {
                if (cum + hist[b] >= kk) break;
                cum += hist[b];
            }
            if (b < 0) b = 0;  // defensive; cannot happen when kk <= candidates
            s_prefix = prefix | (((unsigned long long)(unsigned int)b) << shift);
            s_kk = kk - cum;
        }
        __syncthreads();
        prefix = s_prefix;
        kk     = s_kk;
    }

    // prefix is exactly the kk-th largest key. Keep iff key >= prefix (active only;
    // inactive keys are 0, and the != 0 guard also covers the n_active == 0 row).
    for (int i = tid; i < SS; i += 1024) {
        unsigned long long key = keys[i];
        out[(size_t)row * SS + i] = (key != 0ull && key >= prefix) ? 1.0f : 0.0f;
    }
}

// ---------------------------------------------------------------------------
extern "C" void kernel_launch(void* const* d_in, const int* in_sizes, int n_in,
                              void* d_out, int out_size)
{
    const float4*       hidden = (const float4*)d_in[0];
    const unsigned int* mask   = (const unsigned int*)d_in[1];
    const float4*       w4     = (const float4*)d_in[2];
    const float*        bias   = (const float*)d_in[3];
    float*              out    = (float*)d_out;

    // 64 KB dynamic smem for the key array (idempotent; no static guard)
    cudaFuncSetAttribute(select_kernel,
                         cudaFuncAttributeMaxDynamicSharedMemorySize,
                         SS * (int)sizeof(unsigned long long));

    score_kernel<<<NROWS / 8, 256>>>(hidden, w4, bias);
    select_kernel<<<BB, 1024, SS * sizeof(unsigned long long)>>>(mask, out);
}

// round 4
// speedup vs baseline: 1.2598x; 1.2598x over previous
#include <cuda_runtime.h>
#include <cuda_bf16.h>
#include <cstdint>

// Problem constants
#define BB 8
#define SS 8192
#define DD 1024
#define NROWS (BB * SS)   // 65536 token rows
#define BINS 4096         // 12-bit buckets: sign + 8 exp + 3 mantissa bits
#define BSHIFT 20         // mono >> 20 -> 12-bit bucket

// Scratch (allocation-free rule: __device__ globals)
__device__ float        g_scores[NROWS];
__device__ unsigned int g_hist[BB * BINS];

__device__ __forceinline__ unsigned int mono_of(float s) {
    unsigned int bits = __float_as_uint(s);
    return (bits & 0x80000000u) ? ~bits : (bits | 0x80000000u);
}

// ---------------------------------------------------------------------------
// Kernel 0: zero the histogram (graph replays require re-zeroing every call)
// ---------------------------------------------------------------------------
__global__ void zero_kernel() {
    uint4* p = (uint4*)g_hist;
    int i = blockIdx.x * blockDim.x + threadIdx.x;   // BB*BINS/4 = 8192 uint4
    p[i] = make_uint4(0u, 0u, 0u, 0u);
}

// ---------------------------------------------------------------------------
// Kernel 1: scores[b,s] = dot(hidden[b,s,:], w) + bias; bucket histogram of
// active tokens accumulated via one spread-address global atomic per token.
// One warp per token row; float4 vectorized; warp tree reduction.
// ---------------------------------------------------------------------------
__global__ __launch_bounds__(256) void score_kernel(
    const float4* __restrict__ hidden,        // NROWS * 256 float4
    const unsigned int* __restrict__ active,  // NROWS 32-bit bools
    const float4* __restrict__ w4,            // 256 float4
    const float*  __restrict__ bias)
{
    int gwarp = (blockIdx.x * blockDim.x + threadIdx.x) >> 5;
    int lane  = threadIdx.x & 31;
    if (gwarp >= NROWS) return;

    const float4* row = hidden + (size_t)gwarp * (DD / 4);

    float acc = 0.f;
#pragma unroll
    for (int j = 0; j < 8; ++j) {
        float4 x = __ldg(&row[lane + j * 32]);
        float4 w = __ldg(&w4[lane + j * 32]);
        acc = fmaf(x.x, w.x, acc);
        acc = fmaf(x.y, w.y, acc);
        acc = fmaf(x.z, w.z, acc);
        acc = fmaf(x.w, w.w, acc);
    }
#pragma unroll
    for (int o = 16; o > 0; o >>= 1)
        acc += __shfl_down_sync(0xffffffffu, acc, o);

    if (lane == 0) {
        float s = acc + __ldg(bias);
        g_scores[gwarp] = s;
        if (__ldg(&active[gwarp]) != 0u) {
            int b = gwarp >> 13;  // token / SS
            atomicAdd(&g_hist[b * BINS + (mono_of(s) >> BSHIFT)], 1u);
        }
    }
}

// ---------------------------------------------------------------------------
// Kernel 2: per batch row, pick the top-k using the prebuilt bucket histogram.
//   suffix-scan 4096 bins -> pivot bucket + residual m
//   one pass: bucket > pivot -> keep; bucket == pivot -> candidate
//   exact stable tie resolution among candidates via 64-bit (mono, ~idx) keys
// ---------------------------------------------------------------------------
__global__ __launch_bounds__(1024) void select_kernel(
    const unsigned int* __restrict__ active,  // [BB, SS]
    float* __restrict__ out)                  // [BB, SS] bool as float32
{
    __shared__ unsigned int warp_sums[32];
    __shared__ int s_n;
    __shared__ int s_pivot;
    __shared__ unsigned int s_m;
    __shared__ int s_cnt;
    __shared__ unsigned long long cand[1024];

    const int row  = blockIdx.x;
    const int tid  = threadIdx.x;
    const int lane = tid & 31;
    const int wid  = tid >> 5;

    const unsigned int* hist = g_hist + row * BINS;
    const float*        sc   = g_scores + (size_t)row * SS;
    const unsigned int* am   = active   + (size_t)row * SS;
    float*              op   = out      + (size_t)row * SS;

    if (tid == 0) s_cnt = 0;

    // Thread t covers buckets [(1023-t)*4, (1023-t)*4+3]; ascending t == descending buckets
    uint4 h = __ldg(&((const uint4*)hist)[1023 - tid]);
    unsigned int S = h.x + h.y + h.z + h.w;

    // block inclusive scan over thread sums (t ascending)
    unsigned int inc = S;
#pragma unroll
    for (int o = 1; o < 32; o <<= 1) {
        unsigned int v = __shfl_up_sync(0xffffffffu, inc, o);
        if (lane >= o) inc += v;
    }
    if (lane == 31) warp_sums[wid] = inc;
    __syncthreads();
    if (wid == 0) {
        unsigned int w = warp_sums[lane];
        unsigned int wi = w;
#pragma unroll
        for (int o = 1; o < 32; o <<= 1) {
            unsigned int v = __shfl_up_sync(0xffffffffu, wi, o);
            if (lane >= o) wi += v;
        }
        warp_sums[lane] = wi - w;         // exclusive warp offsets
        if (lane == 31) s_n = (int)wi;    // total active
    }
    __syncthreads();
    inc += warp_sums[wid];
    unsigned int exc = inc - S;

    const int n_active = s_n;
    if (n_active == 0) {
        for (int i = tid; i < SS; i += 1024) op[i] = 0.0f;
        return;
    }
    const unsigned int kk = (unsigned int)max(1, (n_active + 1) >> 1);

    // exactly one thread owns the pivot: exc < kk <= inc
    if (exc < kk && kk <= inc) {
        int base = (1023 - tid) * 4;
        unsigned int cum = exc;
        unsigned int v[4] = { h.w, h.z, h.y, h.x };  // descending bucket order
#pragma unroll
        for (int j = 0; j < 4; ++j) {
            if (cum + v[j] >= kk) { s_pivot = base + 3 - j; s_m = kk - cum; break; }
            cum += v[j];
        }
    }
    __syncthreads();
    const int pivot = s_pivot;
    const unsigned int m = s_m;

    // single pass: write keeps, collect pivot-bucket candidates
    for (int i = tid; i < SS; i += 1024) {
        float o = 0.0f;
        if (am[i] != 0u) {
            unsigned int mono = mono_of(sc[i]);
            int bkt = (int)(mono >> BSHIFT);
            if (bkt > pivot) {
                o = 1.0f;
            } else if (bkt == pivot) {
                int p = atomicAdd(&s_cnt, 1);
                if (p < 1024)
                    cand[p] = (((unsigned long long)mono) << 32)
                            | (unsigned long long)(0xFFFFFFFFu - (unsigned)i);
            }
        }
        op[i] = o;
    }
    __syncthreads();

    // exact stable rank among candidates (mono desc, index asc via ~idx)
    const int C = min(s_cnt, 1024);
    for (int c = tid; c < C; c += 1024) {
        unsigned long long kc = cand[c];
        unsigned int rank = 0;
        for (int j = 0; j < C; ++j)
            rank += (cand[j] > kc);
        if (rank < m) {
            unsigned int idx = 0xFFFFFFFFu - (unsigned int)(kc & 0xFFFFFFFFull);
            op[idx] = 1.0f;
        }
    }
}

// ---------------------------------------------------------------------------
extern "C" void kernel_launch(void* const* d_in, const int* in_sizes, int n_in,
                              void* d_out, int out_size)
{
    const float4*       hidden = (const float4*)d_in[0];
    const unsigned int* mask   = (const unsigned int*)d_in[1];
    const float4*       w4     = (const float4*)d_in[2];
    const float*        bias   = (const float*)d_in[3];
    float*              out    = (float*)d_out;

    zero_kernel<<<(BB * BINS / 4) / 256, 256>>>();
    score_kernel<<<NROWS / 8, 256>>>(hidden, mask, w4, bias);
    select_kernel<<<BB, 1024>>>(mask, out);
}